// round 8
// baseline (speedup 1.0000x reference)
#include <cuda_runtime.h>
#include <cuda_fp16.h>
#include <math_constants.h>

#define NN    100000
#define EDGES 1600000
#define EE    (EDGES + NN)
#define F     128

// ---------------- device scratch (no allocation allowed) ----------------
__device__ uint2 g_hf[NN * 32];  // h = X@W in fp16 (128 halves = 32 uint2/node)
__device__ float g_f0[NN * F];
__device__ float g_f1[NN * F];
__device__ float g_as[NN * 4];
__device__ float g_ad[NN * 4];
__device__ int   g_deg[NN];
__device__ int   g_rs[NN + 1];
__device__ int   g_cnt[NN];
__device__ int   g_src[EE];

// ---------------- CSR build (by destination) ----------------
__global__ void csr_hist(const int* __restrict__ ei, int* __restrict__ deg)
{
    int e = blockIdx.x * blockDim.x + threadIdx.x;
    if (e >= EE) return;
    int d = (e < EDGES) ? ei[EDGES + e] : (e - EDGES);
    atomicAdd(&deg[d], 1);
}

__global__ __launch_bounds__(1024) void csr_scan(const int* __restrict__ deg,
                                                 int* __restrict__ rs)
{
    __shared__ int wsum[32];
    const int t    = threadIdx.x;
    const int lane = t & 31;
    const int w    = t >> 5;
    const int CH   = (NN + 1023) / 1024;
    const int lo   = t * CH;
    const int hi   = min(lo + CH, NN);

    int sum = 0;
    for (int i = lo; i < hi; i++) sum += deg[i];

    int inc = sum;
#pragma unroll
    for (int o = 1; o < 32; o <<= 1) {
        int x = __shfl_up_sync(0xffffffffu, inc, o);
        if (lane >= o) inc += x;
    }
    if (lane == 31) wsum[w] = inc;
    __syncthreads();
    if (w == 0) {
        int v = wsum[lane];
        int s = v;
#pragma unroll
        for (int o = 1; o < 32; o <<= 1) {
            int x = __shfl_up_sync(0xffffffffu, s, o);
            if (lane >= o) s += x;
        }
        wsum[lane] = s - v;
    }
    __syncthreads();

    int run = wsum[w] + inc - sum;
    for (int i = lo; i < hi; i++) { rs[i] = run; run += deg[i]; }
    if (t == 1023) rs[NN] = run;
}

__global__ void csr_fill(const int* __restrict__ ei,
                         const int* __restrict__ rs,
                         int* __restrict__ cnt, int* __restrict__ csrc)
{
    int e = blockIdx.x * blockDim.x + threadIdx.x;
    if (e >= EE) return;
    int s, d;
    if (e < EDGES) { s = ei[e]; d = ei[EDGES + e]; }
    else           { s = d = e - EDGES; }
    int pos = rs[d] + atomicAdd(&cnt[d], 1);
    csrc[pos] = s;
}

// ---------------- register-tiled GEMM + fused attention-logit epilogue -------
// BM=128, BN=128, BK=16, 256 threads (16x16), thread tile 8x8.
__global__ __launch_bounds__(256) void gemm_attn(
    const float* __restrict__ fin, const float* __restrict__ W,
    const float* __restrict__ att_s, const float* __restrict__ att_d,
    uint2* __restrict__ hf, float* __restrict__ as_, float* __restrict__ ad_,
    int H)
{
    __shared__ float  Xs[128][20];     // [row][k], stride 20 (16B-aligned rows)
    __shared__ float4 Ws4[16 * 32];    // [k][col/4]

    const int t    = threadIdx.x;
    const int tx   = t & 15;           // col group: cols tx*8 .. tx*8+7
    const int ty   = t >> 4;           // row group: rows ty*8 .. ty*8+7
    const int row0 = blockIdx.x * 128;

    float acc[8][8];
#pragma unroll
    for (int i = 0; i < 8; i++)
#pragma unroll
        for (int j = 0; j < 8; j++) acc[i][j] = 0.f;

    for (int kc = 0; kc < 8; kc++) {
        // X tile: 128 rows x 16 k  (2 float4 per thread)
#pragma unroll
        for (int i = 0; i < 2; i++) {
            int idx = t + 256 * i;              // 0..511
            int r = idx >> 2, c = idx & 3;
            int gr = min(row0 + r, NN - 1);
            *(float4*)&Xs[r][4 * c] =
                *(const float4*)&fin[gr * F + kc * 16 + 4 * c];
        }
        // W tile: 16 k x 128 cols  (2 float4 per thread)
#pragma unroll
        for (int i = 0; i < 2; i++) {
            int idx = t + 256 * i;              // 0..511
            int k = idx >> 5, c = idx & 31;
            Ws4[k * 32 + c] = *(const float4*)&W[(kc * 16 + k) * F + 4 * c];
        }
        __syncthreads();

#pragma unroll
        for (int k = 0; k < 16; k++) {
            float a[8];
#pragma unroll
            for (int i = 0; i < 8; i++) a[i] = Xs[ty * 8 + i][k];
            float4 b0 = Ws4[k * 32 + tx * 2];
            float4 b1 = Ws4[k * 32 + tx * 2 + 1];
#pragma unroll
            for (int i = 0; i < 8; i++) {
                acc[i][0] += a[i] * b0.x;
                acc[i][1] += a[i] * b0.y;
                acc[i][2] += a[i] * b0.z;
                acc[i][3] += a[i] * b0.w;
                acc[i][4] += a[i] * b1.x;
                acc[i][5] += a[i] * b1.y;
                acc[i][6] += a[i] * b1.z;
                acc[i][7] += a[i] * b1.w;
            }
        }
        __syncthreads();
    }

    // attention vectors for this thread's 8 columns (all in head tx>>2 for H=4)
    float sv[8], dv[8];
#pragma unroll
    for (int j = 0; j < 8; j++) {
        sv[j] = att_s[tx * 8 + j];
        dv[j] = att_d[tx * 8 + j];
    }

#pragma unroll
    for (int i = 0; i < 8; i++) {
        int gr = row0 + ty * 8 + i;
        bool ok = gr < NN;
        if (ok) {
            __half2 p0 = __floats2half2_rn(acc[i][0], acc[i][1]);
            __half2 p1 = __floats2half2_rn(acc[i][2], acc[i][3]);
            __half2 p2 = __floats2half2_rn(acc[i][4], acc[i][5]);
            __half2 p3 = __floats2half2_rn(acc[i][6], acc[i][7]);
            uint4 u;
            u.x = *(unsigned*)&p0; u.y = *(unsigned*)&p1;
            u.z = *(unsigned*)&p2; u.w = *(unsigned*)&p3;
            ((uint4*)hf)[gr * 16 + tx] = u;
        }
        float ps = 0.f, pd = 0.f;
#pragma unroll
        for (int j = 0; j < 8; j++) {
            ps += acc[i][j] * sv[j];
            pd += acc[i][j] * dv[j];
        }
        if (H == 4) {
            // reduce over the 4 tx threads covering one 32-col head
            ps += __shfl_xor_sync(0xffffffffu, ps, 1);
            ps += __shfl_xor_sync(0xffffffffu, ps, 2);
            pd += __shfl_xor_sync(0xffffffffu, pd, 1);
            pd += __shfl_xor_sync(0xffffffffu, pd, 2);
            if ((tx & 3) == 0 && ok) {
                as_[gr * 4 + (tx >> 2)] = ps;
                ad_[gr * 4 + (tx >> 2)] = pd;
            }
        } else {
            // reduce over all 16 tx threads (lane bits 0..3 = tx bits)
#pragma unroll
            for (int o = 1; o < 16; o <<= 1) {
                ps += __shfl_xor_sync(0xffffffffu, ps, o);
                pd += __shfl_xor_sync(0xffffffffu, pd, o);
            }
            if (tx == 0 && ok) { as_[gr] = ps; ad_[gr] = pd; }
        }
    }
}

// ---------------- fused softmax + aggregate: warp per dst node ----------------
// fp16 h gather, fp32 accumulate. Full 8-edge blocks take an unrolled path
// that issues all 8 gather LDGs back-to-back (MLP=8) before the FMAs.
__global__ __launch_bounds__(256) void gat_gather(
    const int* __restrict__ rs, const int* __restrict__ csrc,
    const float* __restrict__ as_, const float* __restrict__ ad_,
    const uint2* __restrict__ hf, const float* __restrict__ b,
    float* __restrict__ out, int H, int elu)
{
    const int warp = (blockIdx.x * blockDim.x + threadIdx.x) >> 5;
    const int lane = threadIdx.x & 31;
    if (warp >= NN) return;
    const int d = warp;

    const int h = (H == 4) ? (lane >> 3) : 0;
    const float adv = ad_[d * H + h];

    float m = -CUDART_INF_F, den = 0.f;
    float4 acc = make_float4(0.f, 0.f, 0.f, 0.f);

    const int start = rs[d], end = rs[d + 1];
    const int gbase = lane & 24;

    for (int j = start; j < end; j += 32) {
        int sj = (j + lane < end) ? csrc[j + lane] : 0;
        int nb = min(32, end - j);
        for (int base = 0; base < nb; base += 8) {
            int nk = min(8, nb - base);
            int  s_my  = __shfl_sync(0xffffffffu, sj, base + (lane & 7));
            bool valid = (lane & 7) < nk;
            float v = -CUDART_INF_F;
            if (valid) {
                float vv = as_[s_my * H + h] + adv;
                v = vv > 0.f ? vv : 0.2f * vv;
            }
            float bm = v;
            bm = fmaxf(bm, __shfl_xor_sync(0xffffffffu, bm, 1));
            bm = fmaxf(bm, __shfl_xor_sync(0xffffffffu, bm, 2));
            bm = fmaxf(bm, __shfl_xor_sync(0xffffffffu, bm, 4));
            float mn = fmaxf(m, bm);
            float f  = __expf(m - mn);
            float p  = valid ? __expf(v - mn) : 0.f;
            float ps = p;
            ps += __shfl_xor_sync(0xffffffffu, ps, 1);
            ps += __shfl_xor_sync(0xffffffffu, ps, 2);
            ps += __shfl_xor_sync(0xffffffffu, ps, 4);
            den = den * f + ps;
            m = mn;
            acc.x *= f; acc.y *= f; acc.z *= f; acc.w *= f;

            if (nk == 8) {
                int   ss[8];
                float pp[8];
#pragma unroll
                for (int k = 0; k < 8; k++) {
                    ss[k] = __shfl_sync(0xffffffffu, sj, base + k);
                    pp[k] = __shfl_sync(0xffffffffu, p, gbase + k);
                }
                uint2 raw[8];
#pragma unroll
                for (int k = 0; k < 8; k++) raw[k] = hf[ss[k] * 32 + lane];
#pragma unroll
                for (int k = 0; k < 8; k++) {
                    float2 f01 = __half22float2(*(__half2*)&raw[k].x);
                    float2 f23 = __half22float2(*(__half2*)&raw[k].y);
                    acc.x += pp[k] * f01.x;
                    acc.y += pp[k] * f01.y;
                    acc.z += pp[k] * f23.x;
                    acc.w += pp[k] * f23.y;
                }
            } else {
                for (int k = 0; k < nk; k++) {
                    int   s  = __shfl_sync(0xffffffffu, sj, base + k);
                    float pk = __shfl_sync(0xffffffffu, p, gbase + k);
                    uint2 raw = hf[s * 32 + lane];
                    float2 f01 = __half22float2(*(__half2*)&raw.x);
                    float2 f23 = __half22float2(*(__half2*)&raw.y);
                    acc.x += pk * f01.x;
                    acc.y += pk * f01.y;
                    acc.z += pk * f23.x;
                    acc.w += pk * f23.y;
                }
            }
        }
    }

    float inv = 1.f / den;
    const float4 bv = ((const float4*)b)[lane];
    float4 o;
    o.x = acc.x * inv + bv.x;
    o.y = acc.y * inv + bv.y;
    o.z = acc.z * inv + bv.z;
    o.w = acc.w * inv + bv.w;
    if (elu) {
        o.x = o.x > 0.f ? o.x : (__expf(o.x) - 1.f);
        o.y = o.y > 0.f ? o.y : (__expf(o.y) - 1.f);
        o.z = o.z > 0.f ? o.z : (__expf(o.z) - 1.f);
        o.w = o.w > 0.f ? o.w : (__expf(o.w) - 1.f);
    }
    ((float4*)out)[d * 32 + lane] = o;
}

// ---------------- host side ----------------
static void run_layer(const float* fin, const float* W, const float* ss,
                      const float* dd, const float* bb, int H, float* outp,
                      int elu, uint2* hf, float* as_, float* ad_,
                      const int* rs, const int* csrc)
{
    gemm_attn<<<(NN + 127) / 128, 256>>>(fin, W, ss, dd, hf, as_, ad_, H);
    gat_gather<<<(NN + 7) / 8, 256>>>(rs, csrc, as_, ad_, hf, bb, outp, H, elu);
}

extern "C" void kernel_launch(void* const* d_in, const int* in_sizes, int n_in,
                              void* d_out, int out_size)
{
    const float* x  = (const float*)d_in[0];
    const int*   ei = (const int*)d_in[1];
    const float* W1 = (const float*)d_in[2];
    const float* s1 = (const float*)d_in[3];
    const float* d1 = (const float*)d_in[4];
    const float* b1 = (const float*)d_in[5];
    const float* W2 = (const float*)d_in[6];
    const float* s2 = (const float*)d_in[7];
    const float* d2 = (const float*)d_in[8];
    const float* b2 = (const float*)d_in[9];
    const float* W3 = (const float*)d_in[10];
    const float* s3 = (const float*)d_in[11];
    const float* d3 = (const float*)d_in[12];
    const float* b3 = (const float*)d_in[13];

    uint2* hf;
    float *f0, *f1, *as_, *ad_;
    int *deg, *rs, *cnt, *csrc;
    cudaGetSymbolAddress((void**)&hf,   g_hf);
    cudaGetSymbolAddress((void**)&f0,   g_f0);
    cudaGetSymbolAddress((void**)&f1,   g_f1);
    cudaGetSymbolAddress((void**)&as_,  g_as);
    cudaGetSymbolAddress((void**)&ad_,  g_ad);
    cudaGetSymbolAddress((void**)&deg,  g_deg);
    cudaGetSymbolAddress((void**)&rs,   g_rs);
    cudaGetSymbolAddress((void**)&cnt,  g_cnt);
    cudaGetSymbolAddress((void**)&csrc, g_src);

    cudaMemsetAsync(deg, 0, NN * sizeof(int));
    cudaMemsetAsync(cnt, 0, NN * sizeof(int));
    const int blk = 256;
    csr_hist<<<(EE + blk - 1) / blk, blk>>>(ei, deg);
    csr_scan<<<1, 1024>>>(deg, rs);
    csr_fill<<<(EE + blk - 1) / blk, blk>>>(ei, rs, cnt, csrc);

    run_layer(x,  W1, s1, d1, b1, 4, f0,            1, hf, as_, ad_, rs, csrc);
    run_layer(f0, W2, s2, d2, b2, 4, f1,            1, hf, as_, ad_, rs, csrc);
    run_layer(f1, W3, s3, d3, b3, 1, (float*)d_out, 0, hf, as_, ad_, rs, csrc);
}